// round 12
// baseline (speedup 1.0000x reference)
#include <cuda_runtime.h>
#include <stdint.h>

// Problem constants (fixed shapes per reference)
#define VOCAB   20000
#define TOPK    8
#define GLOVE   300
#define ROW_F   (TOPK * 2 * GLOVE)   // 4800 floats per vocab row
#define OUTC    100
#define B       32
#define L       128
#define NLAB    8
#define NPOS    (B * L)              // 4096
#define NLABTOT (NPOS * NLAB)        // 32768

#define KSPLIT  5
#define KCH     60                   // 60 % 4 == 0 -> float4-aligned k0
#define PTILE   16                   // halved: 2x more blocks
#define NPT     (NPOS / PTILE)       // 256
#define GT6     100                  // 4 pos-groups x 25 out-groups
#define AP      20
#define WP      104
#define KQ      (KCH / 4)            // 15

// Device scratch (no allocations allowed)
__device__ unsigned int g_flags[VOCAB];
__device__ float g_lsum[VOCAB * GLOVE];            // 24 MB
__device__ float g_part[KSPLIT * NPOS * OUTC];     // 8.2 MB: split-K partials

// ---------------------------------------------------------------------------
// Kernel 1: clear usage flags
// ---------------------------------------------------------------------------
__global__ void k_clear_flags() {
    int i = blockIdx.x * blockDim.x + threadIdx.x;
    if (i < VOCAB) g_flags[i] = 0u;
}

// ---------------------------------------------------------------------------
// Kernel 2: mark used vocab entries
// ---------------------------------------------------------------------------
__global__ void k_mark_flags(const int* __restrict__ labels) {
    int i = blockIdx.x * blockDim.x + threadIdx.x;
    if (i < NLABTOT) g_flags[labels[i]] = 1u;
}

// ---------------------------------------------------------------------------
// Kernel 3: per-vocab row reduction (DRAM floor, ~310 MB @ ~6 TB/s). Proven.
// ---------------------------------------------------------------------------
__global__ __launch_bounds__(256) void k_rowsum(const float* __restrict__ table) {
    const int v = blockIdx.x;
    if (!g_flags[v]) return;
    const float* __restrict__ row = table + (size_t)v * ROW_F;
    const int t = threadIdx.x;
    const float scale = 1.0f / 128.0f;

    {
        float s = 0.0f;
        #pragma unroll
        for (int r = 0; r < 16; ++r) s += row[r * GLOVE + t];
        g_lsum[v * GLOVE + t] = s * scale;
    }
    if (t < GLOVE - 256) {
        const int d = t + 256;
        float s = 0.0f;
        #pragma unroll
        for (int r = 0; r < 16; ++r) s += row[r * GLOVE + d];
        g_lsum[v * GLOVE + d] = s * scale;
    }
}

// ---------------------------------------------------------------------------
// Kernel 4 (v5): split-K GEMM with fused, warp-coalesced float4 gather.
// Grid 1280 = 256 pos-tiles(16) x 5 K-chunks(60): 8.6 blocks/SM (was 4.3).
// 100 threads/block, thread tile 4 pos x 4 outs (unchanged shape).
// W staging vectorized (float4 LDG + 4 STS) to offset the 2x block count.
// smem ~30 KB.
// ---------------------------------------------------------------------------
__global__ __launch_bounds__(GT6) void k_gemm6(
    const int* __restrict__ labels,
    const float* __restrict__ w)          // [100, 300]
{
    __shared__ float A_t[KCH][AP];        // [k][pos]
    __shared__ float W_t[KCH][WP];        // [k][out]
    __shared__ int   s_lab[PTILE * NLAB];

    const int tid   = threadIdx.x;
    const int kc    = blockIdx.x % KSPLIT;
    const int pt    = blockIdx.x / KSPLIT;
    const int pbase = pt * PTILE;
    const int k0    = kc * KCH;

    // stage labels (coalesced)
    for (int i = tid; i < PTILE * NLAB; i += GT6)
        s_lab[i] = labels[pbase * NLAB + i];

    // stage W chunk transposed, float4 over k:
    //   quad j -> (o = j/KQ, kkq = j%KQ); LDG.128 from w, 4 scalar STS.
    for (int j = tid; j < OUTC * KQ; j += GT6) {   // 1500 quads
        const int o   = j / KQ;
        const int kkq = j - o * KQ;
        const int kk  = kkq * 4;
        const float4 v = *reinterpret_cast<const float4*>(
            &w[o * GLOVE + k0 + kk]);
        W_t[kk + 0][o] = v.x;
        W_t[kk + 1][o] = v.y;
        W_t[kk + 2][o] = v.z;
        W_t[kk + 3][o] = v.w;
    }
    __syncthreads();   // labels visible for gather

    // fused float4 gather, pos-major: warp-coalesced LDG.128
    #pragma unroll
    for (int j = tid; j < PTILE * KQ; j += GT6) {   // 240 total
        const int pp  = j / KQ;           // 0..15
        const int kkq = j - pp * KQ;      // 0..14
        const int kg  = k0 + kkq * 4;
        const int* lab = &s_lab[pp * NLAB];
        float4 s = make_float4(0.f, 0.f, 0.f, 0.f);
        #pragma unroll
        for (int m = 0; m < NLAB; ++m) {
            const float4 v = *reinterpret_cast<const float4*>(
                &g_lsum[lab[m] * GLOVE + kg]);
            s.x += v.x; s.y += v.y; s.z += v.z; s.w += v.w;
        }
        const int kk = kkq * 4;
        A_t[kk + 0][pp] = s.x;
        A_t[kk + 1][pp] = s.y;
        A_t[kk + 2][pp] = s.z;
        A_t[kk + 3][pp] = s.w;
    }
    __syncthreads();

    const int pg = tid / 25;   // 0..3 -> pos quad
    const int og = tid % 25;   // 0..24 -> out quad

    float acc[4][4];
    #pragma unroll
    for (int i = 0; i < 4; ++i)
        #pragma unroll
        for (int j = 0; j < 4; ++j) acc[i][j] = 0.0f;

    #pragma unroll 4
    for (int kk = 0; kk < KCH; ++kk) {
        const float4 a  = *reinterpret_cast<const float4*>(&A_t[kk][pg * 4]);
        const float4 wv = *reinterpret_cast<const float4*>(&W_t[kk][og * 4]);
        const float av[4] = {a.x, a.y, a.z, a.w};
        const float wa[4] = {wv.x, wv.y, wv.z, wv.w};
        #pragma unroll
        for (int i = 0; i < 4; ++i)
            #pragma unroll
            for (int j = 0; j < 4; ++j)
                acc[i][j] = fmaf(av[i], wa[j], acc[i][j]);
    }

    // write partials: g_part[kc][pos][out], float4 per pos
    float* dst = g_part + (size_t)kc * (NPOS * OUTC);
    #pragma unroll
    for (int i = 0; i < 4; ++i) {
        const int p = pbase + pg * 4 + i;
        float4 r = make_float4(acc[i][0], acc[i][1], acc[i][2], acc[i][3]);
        *reinterpret_cast<float4*>(&dst[p * OUTC + og * 4]) = r;
    }
}

// ---------------------------------------------------------------------------
// Kernel 5: final reduction of split-K partials + bias.
// ---------------------------------------------------------------------------
#define FIN_THREADS 256
#define FIN_TOTAL   (NPOS * 25)

__global__ __launch_bounds__(FIN_THREADS) void k_final(
    const float* __restrict__ bias,
    float* __restrict__ out)
{
    const int i = blockIdx.x * FIN_THREADS + threadIdx.x;
    if (i >= FIN_TOTAL) return;
    const int p = i / 25;
    const int q = (i % 25) * 4;

    float4 s = *reinterpret_cast<const float4*>(&bias[q]);
    #pragma unroll
    for (int kc = 0; kc < KSPLIT; ++kc) {
        const float4 v = *reinterpret_cast<const float4*>(
            &g_part[(size_t)kc * (NPOS * OUTC) + p * OUTC + q]);
        s.x += v.x; s.y += v.y; s.z += v.z; s.w += v.w;
    }
    *reinterpret_cast<float4*>(&out[p * OUTC + q]) = s;
}

// ---------------------------------------------------------------------------
extern "C" void kernel_launch(void* const* d_in, const int* in_sizes, int n_in,
                              void* d_out, int out_size) {
    const int*   labels = (const int*)  d_in[0];   // [32, 128, 8] int32
    const float* table  = (const float*)d_in[1];   // [20000, 8, 600] f32
    const float* conv_w = (const float*)d_in[2];   // [100, 300]
    const float* conv_b = (const float*)d_in[3];   // [100]
    float*       out    = (float*)d_out;           // [32, 128, 100]

    (void)in_sizes; (void)n_in; (void)out_size;

    k_clear_flags<<<(VOCAB + 255) / 256, 256>>>();
    k_mark_flags<<<(NLABTOT + 255) / 256, 256>>>(labels);
    k_rowsum<<<VOCAB, 256>>>(table);
    k_gemm6<<<NPT * KSPLIT, GT6>>>(labels, conv_w);
    k_final<<<(FIN_TOTAL + FIN_THREADS - 1) / FIN_THREADS, FIN_THREADS>>>(conv_b, out);
}

// round 13
// speedup vs baseline: 1.1793x; 1.1793x over previous
#include <cuda_runtime.h>
#include <stdint.h>

// Problem constants (fixed shapes per reference)
#define VOCAB   20000
#define TOPK    8
#define GLOVE   300
#define ROW_F   (TOPK * 2 * GLOVE)   // 4800 floats per vocab row
#define OUTC    100
#define B       32
#define L       128
#define NLAB    8
#define NPOS    (B * L)              // 4096
#define NLABTOT (NPOS * NLAB)        // 32768

#define KSPLIT  15
#define KCH     20                   // k0 = kc*20, 20 % 4 == 0 -> float4-aligned
#define KQ      (KCH / 4)            // 5
#define PTILE   32
#define NPT     (NPOS / PTILE)       // 128
#define GT6     200
#define AP      36
#define WP      104

// Device scratch (no allocations allowed)
__device__ unsigned int g_flags[VOCAB];
__device__ float g_lsum[VOCAB * GLOVE];            // 24 MB
__device__ float g_part[KSPLIT * NPOS * OUTC];     // 24.6 MB: split-K partials

// ---------------------------------------------------------------------------
// Kernel 1: clear usage flags
// ---------------------------------------------------------------------------
__global__ void k_clear_flags() {
    int i = blockIdx.x * blockDim.x + threadIdx.x;
    if (i < VOCAB) g_flags[i] = 0u;
}

// ---------------------------------------------------------------------------
// Kernel 2: mark used vocab entries
// ---------------------------------------------------------------------------
__global__ void k_mark_flags(const int* __restrict__ labels) {
    int i = blockIdx.x * blockDim.x + threadIdx.x;
    if (i < NLABTOT) g_flags[labels[i]] = 1u;
}

// ---------------------------------------------------------------------------
// Kernel 3: per-vocab row reduction (DRAM floor, ~310 MB @ ~6 TB/s). Proven.
// ---------------------------------------------------------------------------
__global__ __launch_bounds__(256) void k_rowsum(const float* __restrict__ table) {
    const int v = blockIdx.x;
    if (!g_flags[v]) return;
    const float* __restrict__ row = table + (size_t)v * ROW_F;
    const int t = threadIdx.x;
    const float scale = 1.0f / 128.0f;

    {
        float s = 0.0f;
        #pragma unroll
        for (int r = 0; r < 16; ++r) s += row[r * GLOVE + t];
        g_lsum[v * GLOVE + t] = s * scale;
    }
    if (t < GLOVE - 256) {
        const int d = t + 256;
        float s = 0.0f;
        #pragma unroll
        for (int r = 0; r < 16; ++r) s += row[r * GLOVE + d];
        g_lsum[v * GLOVE + d] = s * scale;
    }
}

// ---------------------------------------------------------------------------
// Kernel 4 (v6): split-K GEMM, fused warp-coalesced float4 gather.
// KSPLIT=15, KCH=20 -> grid 1920 = 128 pos-tiles x 15 K-chunks:
// thread-limited ~10 blocks/SM (2000/2048 thr), occ ~98% theoretical.
// W-stage/gather/A traffic invariant in KSPLIT (only k_final grows).
// Labels read DIRECTLY from gmem in the gather (L2-resident, broadcast
// across the 5 lanes sharing a pos) -> no s_lab, single __syncthreads,
// W-stage LDGs and gather LDGs overlap in flight.
// Mainloop: thread tile 4 pos x 4 outs; per k one float4 A + one float4 W.
// smem ~11 KB.
// ---------------------------------------------------------------------------
__global__ __launch_bounds__(GT6) void k_gemm6(
    const int* __restrict__ labels,
    const float* __restrict__ w)          // [100, 300]
{
    __shared__ float A_t[KCH][AP];        // [k][pos]
    __shared__ float W_t[KCH][WP];        // [k][out]

    const int tid   = threadIdx.x;
    const int kc    = blockIdx.x % KSPLIT;
    const int pt    = blockIdx.x / KSPLIT;
    const int pbase = pt * PTILE;
    const int k0    = kc * KCH;

    // ---- stage W chunk transposed, float4 over k (500 quads, 2.5/thread) ----
    for (int j = tid; j < OUTC * KQ; j += GT6) {
        const int o   = j / KQ;
        const int kkq = j - o * KQ;
        const int kk  = kkq * 4;
        const float4 v = *reinterpret_cast<const float4*>(
            &w[o * GLOVE + k0 + kk]);
        W_t[kk + 0][o] = v.x;
        W_t[kk + 1][o] = v.y;
        W_t[kk + 2][o] = v.z;
        W_t[kk + 3][o] = v.w;
    }

    // ---- fused float4 gather, pos-major; labels direct from gmem ----
    // 160 quads: pp = tid/5 (5 lanes share a pos -> label broadcast),
    // kkq = tid%5 -> consecutive lanes cover consecutive k-quads.
    if (tid < PTILE * KQ) {
        const int pp  = tid / KQ;         // 0..31
        const int kkq = tid - pp * KQ;    // 0..4
        const int kg  = k0 + kkq * 4;
        const int* __restrict__ lab = labels + (pbase + pp) * NLAB;
        float4 s = make_float4(0.f, 0.f, 0.f, 0.f);
        #pragma unroll
        for (int m = 0; m < NLAB; ++m) {
            const float4 v = *reinterpret_cast<const float4*>(
                &g_lsum[lab[m] * GLOVE + kg]);
            s.x += v.x; s.y += v.y; s.z += v.z; s.w += v.w;
        }
        const int kk = kkq * 4;
        A_t[kk + 0][pp] = s.x;
        A_t[kk + 1][pp] = s.y;
        A_t[kk + 2][pp] = s.z;
        A_t[kk + 3][pp] = s.w;
    }
    __syncthreads();

    const int pg = tid / 25;   // 0..7 -> pos quad
    const int og = tid % 25;   // 0..24 -> out quad

    float acc[4][4];
    #pragma unroll
    for (int i = 0; i < 4; ++i)
        #pragma unroll
        for (int j = 0; j < 4; ++j) acc[i][j] = 0.0f;

    #pragma unroll
    for (int kk = 0; kk < KCH; ++kk) {
        const float4 a  = *reinterpret_cast<const float4*>(&A_t[kk][pg * 4]);
        const float4 wv = *reinterpret_cast<const float4*>(&W_t[kk][og * 4]);
        const float av[4] = {a.x, a.y, a.z, a.w};
        const float wa[4] = {wv.x, wv.y, wv.z, wv.w};
        #pragma unroll
        for (int i = 0; i < 4; ++i)
            #pragma unroll
            for (int j = 0; j < 4; ++j)
                acc[i][j] = fmaf(av[i], wa[j], acc[i][j]);
    }

    // write partials: g_part[kc][pos][out], float4 per pos
    float* dst = g_part + (size_t)kc * (NPOS * OUTC);
    #pragma unroll
    for (int i = 0; i < 4; ++i) {
        const int p = pbase + pg * 4 + i;
        float4 r = make_float4(acc[i][0], acc[i][1], acc[i][2], acc[i][3]);
        *reinterpret_cast<float4*>(&dst[p * OUTC + og * 4]) = r;
    }
}

// ---------------------------------------------------------------------------
// Kernel 5: final reduction of split-K partials + bias.
// ---------------------------------------------------------------------------
#define FIN_THREADS 256
#define FIN_TOTAL   (NPOS * 25)

__global__ __launch_bounds__(FIN_THREADS) void k_final(
    const float* __restrict__ bias,
    float* __restrict__ out)
{
    const int i = blockIdx.x * FIN_THREADS + threadIdx.x;
    if (i >= FIN_TOTAL) return;
    const int p = i / 25;
    const int q = (i % 25) * 4;

    float4 s = *reinterpret_cast<const float4*>(&bias[q]);
    #pragma unroll
    for (int kc = 0; kc < KSPLIT; ++kc) {
        const float4 v = *reinterpret_cast<const float4*>(
            &g_part[(size_t)kc * (NPOS * OUTC) + p * OUTC + q]);
        s.x += v.x; s.y += v.y; s.z += v.z; s.w += v.w;
    }
    *reinterpret_cast<float4*>(&out[p * OUTC + q]) = s;
}

// ---------------------------------------------------------------------------
extern "C" void kernel_launch(void* const* d_in, const int* in_sizes, int n_in,
                              void* d_out, int out_size) {
    const int*   labels = (const int*)  d_in[0];   // [32, 128, 8] int32
    const float* table  = (const float*)d_in[1];   // [20000, 8, 600] f32
    const float* conv_w = (const float*)d_in[2];   // [100, 300]
    const float* conv_b = (const float*)d_in[3];   // [100]
    float*       out    = (float*)d_out;           // [32, 128, 100]

    (void)in_sizes; (void)n_in; (void)out_size;

    k_clear_flags<<<(VOCAB + 255) / 256, 256>>>();
    k_mark_flags<<<(NLABTOT + 255) / 256, 256>>>(labels);
    k_rowsum<<<VOCAB, 256>>>(table);
    k_gemm6<<<NPT * KSPLIT, GT6>>>(labels, conv_w);
    k_final<<<(FIN_TOTAL + FIN_THREADS - 1) / FIN_THREADS, FIN_THREADS>>>(conv_b, out);
}